// round 1
// baseline (speedup 1.0000x reference)
#include <cuda_runtime.h>

#define THREADS 256
#define BM 32
static constexpr int TSTEPS = 200;

// smem layout (floats): W1[64*256] W3[256*64] b1[256] b2[256] b3[64]
//                       y[32*64] h1[32*256] h2[32*256]
static constexpr int SMEM_FLOATS =
    64*256 + 256*64 + 256 + 256 + 64 + BM*64 + BM*256 + BM*256;
static constexpr size_t SMEM_BYTES = (size_t)SMEM_FLOATS * sizeof(float);

__global__ void __launch_bounds__(THREADS, 1)
neural_ode_kernel(const float* __restrict__ y0,
                  const float* __restrict__ tarr,
                  const float* __restrict__ W1g,
                  const float* __restrict__ b1g,
                  const float* __restrict__ W2g,
                  const float* __restrict__ b2g,
                  const float* __restrict__ W3g,
                  const float* __restrict__ b3g,
                  float* __restrict__ out)
{
    extern __shared__ float sm[];
    float* sW1 = sm;                 // [64][256] row-major
    float* sW3 = sW1 + 64*256;       // [256][64] row-major
    float* sb1 = sW3 + 256*64;       // [256]
    float* sb2 = sb1 + 256;          // [256]
    float* sb3 = sb2 + 256;          // [64]
    float* sy  = sb3 + 64;           // [32][64]
    float* sh1 = sy  + BM*64;        // [32][256]
    float* sh2 = sh1 + BM*256;       // [32][256]

    const int tid  = threadIdx.x;
    const int row0 = blockIdx.x * BM;

    // One-time loads: weights + biases into smem.
    for (int i = tid; i < 64*256; i += THREADS) sW1[i] = W1g[i];
    for (int i = tid; i < 256*64; i += THREADS) sW3[i] = W3g[i];
    if (tid < 256) { sb1[tid] = b1g[tid]; sb2[tid] = b2g[tid]; }
    if (tid < 64)  sb3[tid] = b3g[tid];

    // Load y0 tile; emit t=0 slice of the output.
    for (int i = tid; i < BM*64; i += THREADS) {
        int r = i >> 6, d = i & 63;
        float v = y0[(size_t)(row0 + r) * 64 + d];
        sy[i] = v;
        out[((size_t)(row0 + r) * TSTEPS) * 64 + d] = v;
    }
    const float dt = tarr[1] - tarr[0];
    __syncthreads();

    // GEMM1/GEMM2 thread tiling: 8 rows x 4 cols per thread.
    const int tx = tid & 63;   // col group: cols tx*4 .. tx*4+3 (of 256)
    const int ty = tid >> 6;   // row group: rows ty*8 .. ty*8+7 (of 32)
    // GEMM3 tiling: 2 rows x 4 cols per thread over [32][64].
    const int cx = tid & 15;   // cols cx*4 .. cx*4+3 (of 64)
    const int ry = tid >> 4;   // rows ry*2, ry*2+1 (of 32)

    for (int step = 1; step < TSTEPS; ++step) {
        // ---------- h1 = relu(y @ W1 + b1) : [32][256], K = 64 ----------
        float a1[8][4];
        {
            float bx = sb1[tx*4+0], by = sb1[tx*4+1], bz = sb1[tx*4+2], bw = sb1[tx*4+3];
            #pragma unroll
            for (int i = 0; i < 8; ++i) {
                a1[i][0] = bx; a1[i][1] = by; a1[i][2] = bz; a1[i][3] = bw;
            }
        }
        #pragma unroll 8
        for (int k = 0; k < 64; ++k) {
            float4 w = *(const float4*)(sW1 + k*256 + tx*4);
            #pragma unroll
            for (int i = 0; i < 8; ++i) {
                float yv = sy[(ty*8 + i)*64 + k];
                a1[i][0] += yv * w.x; a1[i][1] += yv * w.y;
                a1[i][2] += yv * w.z; a1[i][3] += yv * w.w;
            }
        }
        #pragma unroll
        for (int i = 0; i < 8; ++i) {
            float4 v;
            v.x = fmaxf(a1[i][0], 0.f); v.y = fmaxf(a1[i][1], 0.f);
            v.z = fmaxf(a1[i][2], 0.f); v.w = fmaxf(a1[i][3], 0.f);
            *(float4*)(sh1 + (ty*8 + i)*256 + tx*4) = v;
        }
        __syncthreads();

        // ---------- h2 = relu(h1 @ W2 + b2) : [32][256], K = 256 ----------
        // W2 streamed from global (L2-resident 256 KB); cross-warp L1 reuse.
        float a2[8][4];
        {
            float bx = sb2[tx*4+0], by = sb2[tx*4+1], bz = sb2[tx*4+2], bw = sb2[tx*4+3];
            #pragma unroll
            for (int i = 0; i < 8; ++i) {
                a2[i][0] = bx; a2[i][1] = by; a2[i][2] = bz; a2[i][3] = bw;
            }
        }
        #pragma unroll 4
        for (int k = 0; k < 256; ++k) {
            float4 w = __ldg((const float4*)(W2g + (size_t)k*256 + tx*4));
            #pragma unroll
            for (int i = 0; i < 8; ++i) {
                float hv = sh1[(ty*8 + i)*256 + k];
                a2[i][0] += hv * w.x; a2[i][1] += hv * w.y;
                a2[i][2] += hv * w.z; a2[i][3] += hv * w.w;
            }
        }
        #pragma unroll
        for (int i = 0; i < 8; ++i) {
            float4 v;
            v.x = fmaxf(a2[i][0], 0.f); v.y = fmaxf(a2[i][1], 0.f);
            v.z = fmaxf(a2[i][2], 0.f); v.w = fmaxf(a2[i][3], 0.f);
            *(float4*)(sh2 + (ty*8 + i)*256 + tx*4) = v;
        }
        __syncthreads();

        // ---------- y += dt * (h2 @ W3 + b3) : [32][64], K = 256 ----------
        float a3[2][4];
        {
            float bx = sb3[cx*4+0], by = sb3[cx*4+1], bz = sb3[cx*4+2], bw = sb3[cx*4+3];
            a3[0][0] = bx; a3[0][1] = by; a3[0][2] = bz; a3[0][3] = bw;
            a3[1][0] = bx; a3[1][1] = by; a3[1][2] = bz; a3[1][3] = bw;
        }
        #pragma unroll 8
        for (int k = 0; k < 256; ++k) {
            float4 w = *(const float4*)(sW3 + k*64 + cx*4);
            #pragma unroll
            for (int i = 0; i < 2; ++i) {
                float hv = sh2[(ry*2 + i)*256 + k];
                a3[i][0] += hv * w.x; a3[i][1] += hv * w.y;
                a3[i][2] += hv * w.z; a3[i][3] += hv * w.w;
            }
        }
        #pragma unroll
        for (int i = 0; i < 2; ++i) {
            int r = ry*2 + i;
            float4 yo = *(const float4*)(sy + r*64 + cx*4);
            float4 yn;
            yn.x = yo.x + dt * a3[i][0];
            yn.y = yo.y + dt * a3[i][1];
            yn.z = yo.z + dt * a3[i][2];
            yn.w = yo.w + dt * a3[i][3];
            *(float4*)(sy + r*64 + cx*4) = yn;
            *(float4*)(out + ((size_t)(row0 + r)*TSTEPS + step)*64 + cx*4) = yn;
        }
        __syncthreads();
    }
}

extern "C" void kernel_launch(void* const* d_in, const int* in_sizes, int n_in,
                              void* d_out, int out_size)
{
    const float* y0 = (const float*)d_in[0];
    const float* t  = (const float*)d_in[1];
    const float* W1 = (const float*)d_in[2];
    const float* b1 = (const float*)d_in[3];
    const float* W2 = (const float*)d_in[4];
    const float* b2 = (const float*)d_in[5];
    const float* W3 = (const float*)d_in[6];
    const float* b3 = (const float*)d_in[7];
    float* out = (float*)d_out;

    cudaFuncSetAttribute(neural_ode_kernel,
                         cudaFuncAttributeMaxDynamicSharedMemorySize,
                         (int)SMEM_BYTES);

    int B = in_sizes[0] / 64;          // 4096
    int grid = B / BM;                 // 128
    neural_ode_kernel<<<grid, THREADS, SMEM_BYTES>>>(
        y0, t, W1, b1, W2, b2, W3, b3, out);
}